// round 8
// baseline (speedup 1.0000x reference)
#include <cuda_runtime.h>

#define N_NODES  100000
#define N_EDGES  3200000
#define N_GRAPHS 1024
#define HID      64
#define NCLS     21
#define NBLK     391   // ceil(N_NODES / 256)

typedef unsigned long long ull;

// ---- scratch ----
__device__ __align__(128) int    g_deg [N_NODES];
__device__ __align__(128) int    g_cursor[N_NODES];
__device__ __align__(128) float  g_agg1[N_NODES];
__device__ __align__(128) int    g_bsum[NBLK];
__device__ __align__(128) float2 g_csrv[N_EDGES];     // (mean1,x) of src, grouped by dst
__device__ __align__(128) float2 g_nf  [N_NODES];     // (mean1, x) per node
__device__ __align__(128) float  g_pool[N_GRAPHS * HID];
__device__ __align__(128) float  g_gcnt[N_GRAPHS];

__device__ __forceinline__ int clamp_node(int i) {
    i = i < 0 ? 0 : i;
    return i >= N_NODES ? N_NODES - 1 : i;
}

// ---- packed fp32x2 helpers ----
__device__ __forceinline__ ull fma2(ull a, ull b, ull c) {
    ull d; asm("fma.rn.f32x2 %0, %1, %2, %3;" : "=l"(d) : "l"(a), "l"(b), "l"(c)); return d;
}
__device__ __forceinline__ float2 unpk2(ull v) {
    float lo, hi; asm("mov.b64 {%0, %1}, %2;" : "=f"(lo), "=f"(hi) : "l"(v));
    return make_float2(lo, hi);
}

// ---- zero accumulators ----
__global__ void zero_kernel() {
    int i = blockIdx.x * blockDim.x + threadIdx.x;
    int stride = gridDim.x * blockDim.x;
    for (int j = i; j < N_NODES; j += stride) { g_deg[j] = 0; g_agg1[j] = 0.0f; }
    for (int j = i; j < N_GRAPHS * HID; j += stride) g_pool[j] = 0.0f;
    for (int j = i; j < N_GRAPHS; j += stride) g_gcnt[j] = 0.0f;
}

// ---- hist: degree + layer-1 scalar sum + graph-count histogram ----
__global__ void hist_kernel(const int* __restrict__ ei,
                            const int* __restrict__ batch,
                            const float* __restrict__ x) {
    int e = blockIdx.x * blockDim.x + threadIdx.x;
    if (e < N_NODES) {
        int b = batch[e];
        b = b < 0 ? 0 : (b >= N_GRAPHS ? N_GRAPHS - 1 : b);
        atomicAdd(&g_gcnt[b], 1.0f);
    }
    if (e >= N_EDGES) return;
    int s = clamp_node(ei[e]);
    int d = clamp_node(ei[N_EDGES + e]);
    atomicAdd(&g_deg[d], 1);
    atomicAdd(&g_agg1[d], x[s]);
}

// ---- scan A: per-block sums of degree ----
__global__ void scanA_kernel() {
    __shared__ int s[256];
    int t = threadIdx.x;
    int i = blockIdx.x * 256 + t;
    s[t] = (i < N_NODES) ? g_deg[i] : 0;
    __syncthreads();
    for (int off = 128; off > 0; off >>= 1) {
        if (t < off) s[t] += s[t + off];
        __syncthreads();
    }
    if (t == 0) g_bsum[blockIdx.x] = s[0];
}

// ---- scan C: block offset (in-block reduce of bsum) + local scan -> cursor;
//      fused elementwise nf = (agg1/deg, x) ----
__global__ void scanC_nf_kernel(const float* __restrict__ x) {
    __shared__ int red[256];
    __shared__ int s[256];
    int t = threadIdx.x;
    int bid = blockIdx.x;

    int acc = 0;
    for (int j = t; j < NBLK; j += 256)
        if (j < bid) acc += g_bsum[j];
    red[t] = acc;
    int i = bid * 256 + t;
    int deg = (i < N_NODES) ? g_deg[i] : 0;
    s[t] = deg;
    __syncthreads();
    for (int off = 128; off > 0; off >>= 1) {
        if (t < off) red[t] += red[t + off];
        __syncthreads();
    }
    int boff = red[0];
    // inclusive scan of s
    for (int off = 1; off < 256; off <<= 1) {
        int tmp = 0;
        if (t >= off) tmp = s[t - off];
        __syncthreads();
        if (t >= off) s[t] += tmp;
        __syncthreads();
    }
    if (i < N_NODES) {
        g_cursor[i] = boff + s[t] - deg;   // exclusive start
        g_nf[i] = make_float2(g_agg1[i] / fmaxf((float)deg, 1.0f), x[i]);
    }
}

// ---- scatter: store src's nf VALUE into dst-grouped CSR ----
__global__ void scatter_kernel(const int* __restrict__ ei) {
    int e = blockIdx.x * blockDim.x + threadIdx.x;
    if (e >= N_EDGES) return;
    int s = clamp_node(ei[e]);
    int d = clamp_node(ei[N_EDGES + e]);
    float2 v = g_nf[s];
    int pos = atomicAdd(&g_cursor[d], 1);
    g_csrv[pos] = v;
}

// ==== fused: agg2 (coalesced value-CSR + on-the-fly h1) -> GEMM -> relu -> pool ====
#define A2STR 66   // float2 stride (528B: 16B-aligned rows, 4-way write conflicts only)
#define SBSTR 68
__global__ __launch_bounds__(256, 4) void h2pool_gemm(
        const int* __restrict__ batch,
        const float* __restrict__ W2l,
        const float* __restrict__ b2,
        const float* __restrict__ W2r,
        const float* __restrict__ W1l,
        const float* __restrict__ b1,
        const float* __restrict__ W1r) {
    __shared__ __align__(16) float2 sA2[64 * A2STR];   // [k][node] duplicated {v,v}
    __shared__ __align__(16) float  sB[64 * SBSTR];    // [k][feat]
    __shared__ int    sBatch[64];
    __shared__ float2 sNF[64];

    int t    = threadIdx.x;
    int lane = t & 31;
    int wid  = t >> 5;
    int n0   = blockIdx.x * 64;
    int tx   = t & 15;
    int ty   = t >> 4;

    if (t < 64) {
        int n = n0 + t;
        int b = -1;
        float2 nf = make_float2(0.0f, 0.0f);
        if (n < N_NODES) {
            b = batch[n];
            b = b < 0 ? 0 : (b >= N_GRAPHS ? N_GRAPHS - 1 : b);
            nf = g_nf[n];
        }
        sBatch[t] = b;
        sNF[t] = nf;
    }

    // fill sB with W2l while phase A runs
#pragma unroll
    for (int i = 0; i < 16; i++) {
        int idx = t + i * 256;
        int f = idx & 63, k = idx >> 6;
        sB[k * SBSTR + f] = W2l[k * HID + f];
    }

    // ---- Phase A: per-warp neighbor-mean of h1, coalesced value-CSR ----
    {
        float wl0 = W1l[lane],      wr0 = W1r[lane],      bb0 = b1[lane];
        float wl1 = W1l[lane + 32], wr1 = W1r[lane + 32], bb1 = b1[lane + 32];
#pragma unroll 1
        for (int r = 0; r < 8; r++) {
            int nl = wid * 8 + r;
            int n  = n0 + nl;
            float acc0 = 0.0f, acc1 = 0.0f;
            int deg = 0;
            if (n < N_NODES) {
                int start = g_cursor[n] ;           // cursor now = row end; recompute start
                deg = g_deg[n];
                start -= deg;                       // original row start
                int end = start + deg;
                for (int j = start; j < end; j += 32) {
                    int idx = j + lane;
                    float2 v = make_float2(0.0f, 0.0f);
                    if (idx < end) v = g_csrv[idx];
                    int m = end - j; if (m > 32) m = 32;
                    if (m == 32) {
#pragma unroll
                        for (int jj = 0; jj < 32; jj++) {
                            float a  = __shfl_sync(0xffffffffu, v.x, jj);
                            float xx = __shfl_sync(0xffffffffu, v.y, jj);
                            acc0 += fmaxf(fmaf(a, wl0, fmaf(xx, wr0, bb0)), 0.0f);
                            acc1 += fmaxf(fmaf(a, wl1, fmaf(xx, wr1, bb1)), 0.0f);
                        }
                    } else {
                        for (int jj = 0; jj < m; jj++) {
                            float a  = __shfl_sync(0xffffffffu, v.x, jj);
                            float xx = __shfl_sync(0xffffffffu, v.y, jj);
                            acc0 += fmaxf(fmaf(a, wl0, fmaf(xx, wr0, bb0)), 0.0f);
                            acc1 += fmaxf(fmaf(a, wl1, fmaf(xx, wr1, bb1)), 0.0f);
                        }
                    }
                }
            }
            float inv = 1.0f / fmaxf((float)deg, 1.0f);
            float v0 = acc0 * inv, v1 = acc1 * inv;
            sA2[lane * A2STR + nl]        = make_float2(v0, v0);
            sA2[(lane + 32) * A2STR + nl] = make_float2(v1, v1);
        }
    }
    __syncthreads();

    // ---- Phase B: GEMM, 2 K-chunks, packed f32x2 FMA, duplicated-a tiles ----
    ull acc2[4][2] = {};
#pragma unroll
    for (int ch = 0; ch < 2; ch++) {
#pragma unroll
        for (int k = 0; k < 64; k++) {
            ulonglong2 a01 = *(const ulonglong2*)&sA2[k * A2STR + ty * 4];
            ulonglong2 a23 = *(const ulonglong2*)&sA2[k * A2STR + ty * 4 + 2];
            ulonglong2 b   = *(const ulonglong2*)&sB[k * SBSTR + tx * 4];
            acc2[0][0] = fma2(a01.x, b.x, acc2[0][0]); acc2[0][1] = fma2(a01.x, b.y, acc2[0][1]);
            acc2[1][0] = fma2(a01.y, b.x, acc2[1][0]); acc2[1][1] = fma2(a01.y, b.y, acc2[1][1]);
            acc2[2][0] = fma2(a23.x, b.x, acc2[2][0]); acc2[2][1] = fma2(a23.x, b.y, acc2[2][1]);
            acc2[3][0] = fma2(a23.y, b.x, acc2[3][0]); acc2[3][1] = fma2(a23.y, b.y, acc2[3][1]);
        }
        __syncthreads();
        if (ch == 0) {
            // refill sA2 with on-the-fly h1 (duplicated), sB with W2r
#pragma unroll
            for (int i = 0; i < 16; i++) {
                int idx = t + i * 256;
                int f = idx & 63, n = idx >> 6;
                float2 nf = sNF[n];
                float v = fmaxf(fmaf(nf.x, W1l[f], fmaf(nf.y, W1r[f], b1[f])), 0.0f);
                if (n0 + n >= N_NODES) v = 0.0f;
                sA2[f * A2STR + n] = make_float2(v, v);
            }
#pragma unroll
            for (int i = 0; i < 16; i++) {
                int idx = t + i * 256;
                int f = idx & 63, k = idx >> 6;
                sB[k * SBSTR + f] = W2r[k * HID + f];
            }
            __syncthreads();
        }
    }

    // ---- Phase C: bias + relu -> stage h2 into sB [node][feat], then pool ----
#pragma unroll
    for (int i = 0; i < 4; i++) {
        float2 p0 = unpk2(acc2[i][0]);
        float2 p1 = unpk2(acc2[i][1]);
        int nrow = (ty * 4 + i) * SBSTR + tx * 4;
        sB[nrow + 0] = fmaxf(p0.x + b2[tx * 4 + 0], 0.0f);
        sB[nrow + 1] = fmaxf(p0.y + b2[tx * 4 + 1], 0.0f);
        sB[nrow + 2] = fmaxf(p1.x + b2[tx * 4 + 2], 0.0f);
        sB[nrow + 3] = fmaxf(p1.y + b2[tx * 4 + 3], 0.0f);
    }
    __syncthreads();

    {
        int f = t & 63;
        int g = t >> 6;
        int cur = -2;
        float racc = 0.0f;
#pragma unroll
        for (int i = 0; i < 16; i++) {
            int n = g * 16 + i;
            int b = sBatch[n];
            if (b != cur) {
                if (cur >= 0) atomicAdd(&g_pool[cur * HID + f], racc);
                racc = 0.0f;
                cur = b;
            }
            if (b >= 0) racc += sB[n * SBSTR + f];
        }
        if (cur >= 0) atomicAdd(&g_pool[cur * HID + f], racc);
    }
}

// ---- classifier ----
__global__ void final_kernel(const float* __restrict__ Wc,
                             const float* __restrict__ bc,
                             float* __restrict__ out) {
    int g = blockIdx.x;
    int cid = threadIdx.x;
    if (cid >= NCLS) return;
    float inv = 1.0f / fmaxf(g_gcnt[g], 1.0f);
    float acc = bc[cid];
#pragma unroll
    for (int k = 0; k < HID; k++) {
        acc += g_pool[g * HID + k] * inv * Wc[k * NCLS + cid];
    }
    out[g * NCLS + cid] = acc;
}

extern "C" void kernel_launch(void* const* d_in, const int* in_sizes, int n_in,
                              void* d_out, int out_size) {
    const float* x    = (const float*)d_in[0];
    const int*   ei   = (const int*)d_in[1];
    const int*   bat  = (const int*)d_in[2];
    const float* W1l  = (const float*)d_in[3];
    const float* b1   = (const float*)d_in[4];
    const float* W1r  = (const float*)d_in[5];
    const float* W2l  = (const float*)d_in[6];
    const float* b2   = (const float*)d_in[7];
    const float* W2r  = (const float*)d_in[8];
    const float* Wc   = (const float*)d_in[9];
    const float* bc   = (const float*)d_in[10];
    float*       out  = (float*)d_out;

    (void)in_sizes; (void)n_in; (void)out_size;

    zero_kernel<<<1024, 256>>>();
    hist_kernel<<<(N_EDGES + 255) / 256, 256>>>(ei, bat, x);
    scanA_kernel<<<NBLK, 256>>>();
    scanC_nf_kernel<<<NBLK, 256>>>(x);
    scatter_kernel<<<(N_EDGES + 255) / 256, 256>>>(ei);
    h2pool_gemm<<<(N_NODES + 63) / 64, 256>>>(bat, W2l, b2, W2r, W1l, b1, W1r);
    final_kernel<<<N_GRAPHS, 32>>>(Wc, bc, out);
}